// round 4
// baseline (speedup 1.0000x reference)
#include <cuda_runtime.h>
#include <cuda_bf16.h>
#include <cstdint>

#define VOCAB 50257
#define DM 768
#define NE 4
#define RR 32
#define BB 4
#define TT 512
#define NTOK (BB*TT)   // 2048

// ---------------- scratch (static device arrays; no allocation) ----------------
__device__ float g_x[NTOK*DM];        // gathered embeddings [n][d]
__device__ float g_pre[NTOK*NE*RR];   // x @ W_in, [n][e*32+r]
__device__ int   g_win[NTOK];         // argmax expert per token
__device__ float g_cand[NTOK*RR];     // winner's cand per token
__device__ float g_h[NTOK*DM];        // post-LN activations

// =================================================================
// K1: embedding gather + pre = x@W_in (all experts) + routing argmax
// block = 256 threads, 32 tokens; K-chunked GEMM 32x128, K=768
// =================================================================
__global__ void __launch_bounds__(256) k1_embed_route(
    const int* __restrict__ idx, const float* __restrict__ Wemb,
    const float* __restrict__ G, const float* __restrict__ Win)
{
    __shared__ float xs[32][36];     // x chunk [tok][k], padded
    __shared__ float Ws[32][132];    // W_in chunk [k][e*32+r], padded
    __shared__ float Gs[NE][32];
    __shared__ float sc[32][NE];

    const int tid = threadIdx.x;
    const int n0  = blockIdx.x * 32;

    float acc[4][4];
#pragma unroll
    for (int i = 0; i < 4; i++)
#pragma unroll
        for (int j = 0; j < 4; j++) acc[i][j] = 0.f;
    float accs = 0.f;

    const int tm = (tid >> 5) << 2;      // 4-token group
    const int tn = (tid & 31) << 2;      // 4-col group

    const int lrow = tid >> 3;           // 0..31 (token for x load)
    const int lk   = (tid & 7) << 2;     // k offset *4
    const float* xsrc = Wemb + (size_t)idx[n0 + lrow] * DM + lk;
    float*       xdst = g_x  + (size_t)(n0 + lrow) * DM + lk;

    const int i0 = tid * 16;             // W_in loader mapping
    const int wk = i0 >> 7;              // k within chunk
    const int wc = i0 & 127;             // col start (multiple of 16)
    const int we = wc >> 5;
    const int wr = wc & 31;

    for (int kc = 0; kc < DM; kc += 32) {
        // x chunk (gather) + persist to g_x
        float4 xv = *(const float4*)(xsrc + kc);
        *(float4*)&xs[lrow][lk] = xv;
        *(float4*)(xdst + kc)   = xv;
        // W_in chunk: 16 consecutive floats per thread (same k, same expert run)
        const float* wsrc = Win + (size_t)we * DM * RR + (size_t)(kc + wk) * RR + wr;
#pragma unroll
        for (int j = 0; j < 4; j++)
            *(float4*)&Ws[wk][wc + 4*j] = *(const float4*)(wsrc + 4*j);
        // G chunk
        if (tid >= 128) {
            int j = tid - 128; int e = j >> 5; int r = j & 31;
            Gs[e][r] = G[e * DM + kc + r];
        }
        __syncthreads();

#pragma unroll
        for (int k = 0; k < 32; k++) {
            float4 bv = *(float4*)&Ws[k][tn];
            float a0 = xs[tm+0][k], a1 = xs[tm+1][k], a2 = xs[tm+2][k], a3 = xs[tm+3][k];
            acc[0][0] += a0*bv.x; acc[0][1] += a0*bv.y; acc[0][2] += a0*bv.z; acc[0][3] += a0*bv.w;
            acc[1][0] += a1*bv.x; acc[1][1] += a1*bv.y; acc[1][2] += a1*bv.z; acc[1][3] += a1*bv.w;
            acc[2][0] += a2*bv.x; acc[2][1] += a2*bv.y; acc[2][2] += a2*bv.z; acc[2][3] += a2*bv.w;
            acc[3][0] += a3*bv.x; acc[3][1] += a3*bv.y; acc[3][2] += a3*bv.z; acc[3][3] += a3*bv.w;
        }
        if (tid < 128) {
            int tok = tid >> 2, e = tid & 3;
#pragma unroll
            for (int k = 0; k < 32; k++) accs += xs[tok][k] * Gs[e][k];
        }
        __syncthreads();
    }

#pragma unroll
    for (int i = 0; i < 4; i++) {
        float4 v = make_float4(acc[i][0], acc[i][1], acc[i][2], acc[i][3]);
        *(float4*)&g_pre[(size_t)(n0 + tm + i) * (NE*RR) + tn] = v;
    }
    if (tid < 128) sc[tid >> 2][tid & 3] = accs;
    __syncthreads();
    if (tid < 32) {
        float best = sc[tid][0]; int be = 0;
#pragma unroll
        for (int e = 1; e < 4; e++) { float v = sc[tid][e]; if (v > best) { best = v; be = e; } }
        g_win[n0 + tid] = be;
    }
}

// =================================================================
// K2: sequential recurrent scan. 1 warp per batch b; state in regs.
// Only the winner's cand is needed per step.
// =================================================================
__global__ void __launch_bounds__(32) k2_scan(const float* __restrict__ Wrec)
{
    __shared__ float ws[NE * RR * RR];   // [e][r][s]
    __shared__ int   win_s[TT];

    const int b    = blockIdx.x;
    const int lane = threadIdx.x;

    for (int i = lane * 4; i < NE*RR*RR; i += 128)
        *(float4*)&ws[i] = *(const float4*)&Wrec[i];
    for (int i = lane; i < TT; i += 32)
        win_s[i] = g_win[b * TT + i];
    __syncwarp();

    float st0 = 0.f, st1 = 0.f, st2 = 0.f, st3 = 0.f;
    const float* preb = g_pre + (size_t)b * TT * (NE*RR);

    float pr[8];
#pragma unroll
    for (int i = 0; i < 8; i++)
        pr[i] = preb[i * (NE*RR) + win_s[i] * RR + lane];

    for (int tb = 0; tb < TT; tb += 8) {
#pragma unroll
        for (int i = 0; i < 8; i++) {
            const int t = tb + i;
            const int e = win_s[t];
            float se = (e == 0) ? st0 : (e == 1) ? st1 : (e == 2) ? st2 : st3;
            const float* wb = ws + e * (RR*RR);
            float a0 = pr[i], a1 = 0.f, a2 = 0.f, a3 = 0.f;
#pragma unroll
            for (int r = 0; r < RR; r += 4) {
                a0 += __shfl_sync(0xffffffffu, se, r)     * wb[(r    ) * RR + lane];
                a1 += __shfl_sync(0xffffffffu, se, r + 1) * wb[(r + 1) * RR + lane];
                a2 += __shfl_sync(0xffffffffu, se, r + 2) * wb[(r + 2) * RR + lane];
                a3 += __shfl_sync(0xffffffffu, se, r + 3) * wb[(r + 3) * RR + lane];
            }
            float c = tanhf((a0 + a1) + (a2 + a3));
            g_cand[(size_t)(b * TT + t) * RR + lane] = c;
            if      (e == 0) st0 = c;
            else if (e == 1) st1 = c;
            else if (e == 2) st2 = c;
            else             st3 = c;
            const int tnx = t + 8;
            pr[i] = (tnx < TT) ? preb[tnx * (NE*RR) + win_s[tnx] * RR + lane] : 0.f;
        }
    }
}

// =================================================================
// K3: y = cand @ W_out[e] + x, then LayerNorm -> g_h. 1 block/token.
// =================================================================
__global__ void __launch_bounds__(256) k3_out_ln(
    const float* __restrict__ Wout,
    const float* __restrict__ gamma, const float* __restrict__ beta)
{
    const int n = blockIdx.x;
    const int tid = threadIdx.x;
    __shared__ float cs[RR];
    __shared__ float ssum[8], sqq[8];

    const int e = g_win[n];
    if (tid < RR) cs[tid] = g_cand[(size_t)n * RR + tid];
    __syncthreads();

    const float* wo = Wout + (size_t)e * RR * DM;
    float y[3];
#pragma unroll
    for (int j = 0; j < 3; j++) {
        const int d = tid + j * 256;
        float a = g_x[(size_t)n * DM + d];
#pragma unroll
        for (int r = 0; r < RR; r++) a += cs[r] * wo[r * DM + d];
        y[j] = a;
    }
    float s = y[0] + y[1] + y[2];
    float q = y[0]*y[0] + y[1]*y[1] + y[2]*y[2];
#pragma unroll
    for (int o = 16; o; o >>= 1) {
        s += __shfl_xor_sync(0xffffffffu, s, o);
        q += __shfl_xor_sync(0xffffffffu, q, o);
    }
    if ((tid & 31) == 0) { ssum[tid >> 5] = s; sqq[tid >> 5] = q; }
    __syncthreads();
    float st = 0.f, qt = 0.f;
#pragma unroll
    for (int i = 0; i < 8; i++) { st += ssum[i]; qt += sqq[i]; }
    const float mean = st * (1.0f / DM);
    const float var  = qt * (1.0f / DM) - mean * mean;
    const float inv  = rsqrtf(var + 1e-5f);
#pragma unroll
    for (int j = 0; j < 3; j++) {
        const int d = tid + j * 256;
        g_h[(size_t)n * DM + d] = (y[j] - mean) * inv * gamma[d] + beta[d];
    }
}

// =================================================================
// K4: logits = h @ W_emb^T, TF32 mma.sync, 128x128x32 tiles, cp.async
// =================================================================
#define BM 128
#define BN 128
#define BK 32
#define TSTR 36                  // smem row stride (floats), 16B aligned, conflict-free
#define STAGE_F (2 * BM * TSTR)  // floats per stage (A + B)

__device__ __forceinline__ void cp16(float* dst, const float* src) {
    unsigned d = (unsigned)__cvta_generic_to_shared(dst);
    asm volatile("cp.async.cg.shared.global [%0], [%1], 16;\n" :: "r"(d), "l"(src));
}
__device__ __forceinline__ void cp16p(float* dst, const float* src, bool valid) {
    unsigned d = (unsigned)__cvta_generic_to_shared(dst);
    int sz = valid ? 16 : 0;
    asm volatile("cp.async.cg.shared.global [%0], [%1], 16, %2;\n" :: "r"(d), "l"(src), "r"(sz));
}
__device__ __forceinline__ unsigned f2tf(float x) {
    unsigned r; asm("cvt.rna.tf32.f32 %0, %1;" : "=r"(r) : "f"(x)); return r;
}
__device__ __forceinline__ void mma8(float c[4], const unsigned a[4], const unsigned b[2]) {
    asm volatile(
        "mma.sync.aligned.m16n8k8.row.col.f32.tf32.tf32.f32 "
        "{%0,%1,%2,%3}, {%4,%5,%6,%7}, {%8,%9}, {%0,%1,%2,%3};"
        : "+f"(c[0]), "+f"(c[1]), "+f"(c[2]), "+f"(c[3])
        : "r"(a[0]), "r"(a[1]), "r"(a[2]), "r"(a[3]), "r"(b[0]), "r"(b[1]));
}

__global__ void __launch_bounds__(256) k4_head(
    const float* __restrict__ Wemb, float* __restrict__ out)
{
    extern __shared__ float sm[];
    const int tid  = threadIdx.x;
    const int n0   = blockIdx.x * BN;
    const int m0   = blockIdx.y * BM;
    const int warp = tid >> 5, lane = tid & 31;
    const int wm = warp & 1, wn = warp >> 1;
    const int grp = lane >> 2, tig = lane & 3;

    float c[4][4][4];
#pragma unroll
    for (int i = 0; i < 4; i++)
#pragma unroll
        for (int j = 0; j < 4; j++)
#pragma unroll
            for (int v = 0; v < 4; v++) c[i][j][v] = 0.f;

    const int lrow = tid >> 3;
    const int lk   = (tid & 7) << 2;
    const float* asrc = g_h + (size_t)(m0 + lrow) * DM + lk;

    auto load_stage = [&](int s, int k0) {
        float* As = sm + s * STAGE_F;
        float* Bs = As + BM * TSTR;
#pragma unroll
        for (int p = 0; p < 4; p++) {
            const int r = lrow + p * 32;
            cp16(&As[r * TSTR + lk], asrc + k0 + (size_t)p * 32 * DM);
            const int nrow = n0 + r;
            const int nclamp = nrow < VOCAB ? nrow : VOCAB - 1;
            cp16p(&Bs[r * TSTR + lk], Wemb + (size_t)nclamp * DM + k0 + lk, nrow < VOCAB);
        }
    };

    load_stage(0, 0);
    asm volatile("cp.async.commit_group;\n" ::: "memory");

    const int NIT = DM / BK;  // 24
    for (int it = 0; it < NIT; it++) {
        __syncthreads();   // prev compute done before overwriting its stage
        if (it + 1 < NIT) {
            load_stage((it + 1) & 1, (it + 1) * BK);
            asm volatile("cp.async.commit_group;\n" ::: "memory");
            asm volatile("cp.async.wait_group 1;\n" ::: "memory");
        } else {
            asm volatile("cp.async.wait_group 0;\n" ::: "memory");
        }
        __syncthreads();   // stage `it` visible to all

        const float* As = sm + (it & 1) * STAGE_F;
        const float* Bs = As + BM * TSTR;
#pragma unroll
        for (int ks = 0; ks < 4; ks++) {
            const int kk = ks * 8;
            unsigned af[4][4];
#pragma unroll
            for (int mf = 0; mf < 4; mf++) {
                const int rm = wm * 64 + mf * 16 + grp;
                af[mf][0] = f2tf(As[(rm    ) * TSTR + kk + tig    ]);
                af[mf][1] = f2tf(As[(rm + 8) * TSTR + kk + tig    ]);
                af[mf][2] = f2tf(As[(rm    ) * TSTR + kk + tig + 4]);
                af[mf][3] = f2tf(As[(rm + 8) * TSTR + kk + tig + 4]);
            }
            unsigned bf[4][2];
#pragma unroll
            for (int nf = 0; nf < 4; nf++) {
                const int cn = wn * 32 + nf * 8 + grp;
                bf[nf][0] = f2tf(Bs[cn * TSTR + kk + tig    ]);
                bf[nf][1] = f2tf(Bs[cn * TSTR + kk + tig + 4]);
            }
#pragma unroll
            for (int mf = 0; mf < 4; mf++)
#pragma unroll
                for (int nf = 0; nf < 4; nf++)
                    mma8(c[mf][nf], af[mf], bf[nf]);
        }
    }

    // epilogue (scalar guarded stores; VOCAB is odd so float2 can misalign)
#pragma unroll
    for (int mf = 0; mf < 4; mf++) {
        const int row = m0 + wm * 64 + mf * 16 + grp;
#pragma unroll
        for (int nf = 0; nf < 4; nf++) {
            const int col = n0 + wn * 32 + nf * 8 + (tig << 1);
            float* p0 = out + (size_t)row * VOCAB + col;
            float* p1 = p0 + (size_t)8 * VOCAB;
            if (col < VOCAB)     { p0[0] = c[mf][nf][0]; p1[0] = c[mf][nf][2]; }
            if (col + 1 < VOCAB) { p0[1] = c[mf][nf][1]; p1[1] = c[mf][nf][3]; }
        }
    }
}

// =================================================================
extern "C" void kernel_launch(void* const* d_in, const int* in_sizes, int n_in,
                              void* d_out, int out_size)
{
    const int*   idx   = (const int*)  d_in[0];
    const float* Wemb  = (const float*)d_in[1];
    const float* G     = (const float*)d_in[2];
    const float* Win   = (const float*)d_in[3];
    const float* Wrec  = (const float*)d_in[4];
    const float* Wout  = (const float*)d_in[5];
    const float* gamma = (const float*)d_in[6];
    const float* beta  = (const float*)d_in[7];
    float* out = (float*)d_out;

    k1_embed_route<<<NTOK / 32, 256>>>(idx, Wemb, G, Win);
    k2_scan<<<BB, 32>>>(Wrec);
    k3_out_ln<<<NTOK, 256>>>(Wout, gamma, beta);

    const int smem = STAGE_F * 2 * (int)sizeof(float);  // 73728 B
    cudaFuncSetAttribute(k4_head, cudaFuncAttributeMaxDynamicSharedMemorySize, smem);
    dim3 g4((VOCAB + BN - 1) / BN, NTOK / BM);
    k4_head<<<g4, 256, smem>>>(Wemb, out);
}

// round 10
// speedup vs baseline: 1.2279x; 1.2279x over previous
#include <cuda_runtime.h>
#include <cuda_fp16.h>
#include <cstdint>

#define VOCAB 50257
#define DM 768
#define NE 4
#define RR 32
#define BB 4
#define TT 512
#define NTOK (BB*TT)   // 2048

// ---------------- scratch (static device arrays; no allocation) ----------------
__device__ float  g_x[NTOK*DM];        // gathered embeddings [n][d] fp32
__device__ float  g_pre[NTOK*NE*RR];   // x @ W_in, [n][e*32+r]
__device__ int    g_win[NTOK];         // argmax expert per token
__device__ float  g_cand[NTOK*RR];     // winner's cand per token
__device__ __half g_hh[NTOK*DM];       // post-LN activations, fp16 (rna)
__device__ __half g_wh[VOCAB*DM];      // Wemb in fp16 (rna)

// =================================================================
// K0: Wemb fp32 -> fp16 (round-to-nearest)
// =================================================================
__global__ void __launch_bounds__(256) k0_convert(const float4* __restrict__ src)
{
    const int i = blockIdx.x * 256 + threadIdx.x;
    if (i < VOCAB * DM / 4) {
        float4 v = src[i];
        __half2 h0 = __floats2half2_rn(v.x, v.y);
        __half2 h1 = __floats2half2_rn(v.z, v.w);
        uint2 o;
        o.x = *(unsigned*)&h0;
        o.y = *(unsigned*)&h1;
        *(uint2*)&g_wh[(size_t)i * 4] = o;
    }
}

// =================================================================
// K1: embedding gather + pre = x@W_in (all experts) + routing argmax
// =================================================================
__global__ void __launch_bounds__(256) k1_embed_route(
    const int* __restrict__ idx, const float* __restrict__ Wemb,
    const float* __restrict__ G, const float* __restrict__ Win)
{
    __shared__ float xs[32][36];
    __shared__ float Ws[32][132];
    __shared__ float Gs[NE][32];
    __shared__ float sc[32][NE];

    const int tid = threadIdx.x;
    const int n0  = blockIdx.x * 32;

    float acc[4][4];
#pragma unroll
    for (int i = 0; i < 4; i++)
#pragma unroll
        for (int j = 0; j < 4; j++) acc[i][j] = 0.f;
    float accs = 0.f;

    const int tm = (tid >> 5) << 2;
    const int tn = (tid & 31) << 2;

    const int lrow = tid >> 3;
    const int lk   = (tid & 7) << 2;
    const float* xsrc = Wemb + (size_t)idx[n0 + lrow] * DM + lk;
    float*       xdst = g_x  + (size_t)(n0 + lrow) * DM + lk;

    const int i0 = tid * 16;
    const int wk = i0 >> 7;
    const int wc = i0 & 127;
    const int we = wc >> 5;
    const int wr = wc & 31;

    for (int kc = 0; kc < DM; kc += 32) {
        float4 xv = *(const float4*)(xsrc + kc);
        *(float4*)&xs[lrow][lk] = xv;
        *(float4*)(xdst + kc)   = xv;
        const float* wsrc = Win + (size_t)we * DM * RR + (size_t)(kc + wk) * RR + wr;
#pragma unroll
        for (int j = 0; j < 4; j++)
            *(float4*)&Ws[wk][wc + 4*j] = *(const float4*)(wsrc + 4*j);
        if (tid >= 128) {
            int j = tid - 128; int e = j >> 5; int r = j & 31;
            Gs[e][r] = G[e * DM + kc + r];
        }
        __syncthreads();

#pragma unroll
        for (int k = 0; k < 32; k++) {
            float4 bv = *(float4*)&Ws[k][tn];
            float a0 = xs[tm+0][k], a1 = xs[tm+1][k], a2 = xs[tm+2][k], a3 = xs[tm+3][k];
            acc[0][0] += a0*bv.x; acc[0][1] += a0*bv.y; acc[0][2] += a0*bv.z; acc[0][3] += a0*bv.w;
            acc[1][0] += a1*bv.x; acc[1][1] += a1*bv.y; acc[1][2] += a1*bv.z; acc[1][3] += a1*bv.w;
            acc[2][0] += a2*bv.x; acc[2][1] += a2*bv.y; acc[2][2] += a2*bv.z; acc[2][3] += a2*bv.w;
            acc[3][0] += a3*bv.x; acc[3][1] += a3*bv.y; acc[3][2] += a3*bv.z; acc[3][3] += a3*bv.w;
        }
        if (tid < 128) {
            int tok = tid >> 2, e = tid & 3;
#pragma unroll
            for (int k = 0; k < 32; k++) accs += xs[tok][k] * Gs[e][k];
        }
        __syncthreads();
    }

#pragma unroll
    for (int i = 0; i < 4; i++) {
        float4 v = make_float4(acc[i][0], acc[i][1], acc[i][2], acc[i][3]);
        *(float4*)&g_pre[(size_t)(n0 + tm + i) * (NE*RR) + tn] = v;
    }
    if (tid < 128) sc[tid >> 2][tid & 3] = accs;
    __syncthreads();
    if (tid < 32) {
        float best = sc[tid][0]; int be = 0;
#pragma unroll
        for (int e = 1; e < 4; e++) { float v = sc[tid][e]; if (v > best) { best = v; be = e; } }
        g_win[n0 + tid] = be;
    }
}

// =================================================================
// K2: per-expert chains are independent -> 1 warp per (batch, expert).
// =================================================================
__global__ void __launch_bounds__(128) k2_scan(const float* __restrict__ Wrec)
{
    __shared__ float ws[NE * RR * RR];
    __shared__ int   win_s[TT];
    __shared__ short lst[NE][TT];

    const int b = blockIdx.x, tid = threadIdx.x;
    const int w = tid >> 5, lane = tid & 31;

    for (int i = tid * 4; i < NE*RR*RR; i += 512)
        *(float4*)&ws[i] = *(const float4*)&Wrec[i];
    for (int i = tid; i < TT; i += 128)
        win_s[i] = g_win[b * TT + i];
    __syncthreads();

    int cnt = 0;
    for (int t0 = 0; t0 < TT; t0 += 32) {
        bool m = (win_s[t0 + lane] == w);
        unsigned bal = __ballot_sync(0xffffffffu, m);
        if (m) lst[w][cnt + __popc(bal & ((1u << lane) - 1u))] = (short)(t0 + lane);
        cnt += __popc(bal);
    }
    __syncwarp();

    const float* wb   = ws + w * (RR*RR);
    const float* preb = g_pre + (size_t)b * TT * (NE*RR) + w * RR + lane;

    float st = 0.f;
    float nxt = cnt ? preb[(int)lst[w][0] * (NE*RR)] : 0.f;
    for (int k = 0; k < cnt; k++) {
        const int t = lst[w][k];
        float pv = nxt;
        nxt = (k + 1 < cnt) ? preb[(int)lst[w][k + 1] * (NE*RR)] : 0.f;
        float a0 = pv, a1 = 0.f, a2 = 0.f, a3 = 0.f;
#pragma unroll
        for (int r = 0; r < RR; r += 4) {
            a0 += __shfl_sync(0xffffffffu, st, r)     * wb[(r    ) * RR + lane];
            a1 += __shfl_sync(0xffffffffu, st, r + 1) * wb[(r + 1) * RR + lane];
            a2 += __shfl_sync(0xffffffffu, st, r + 2) * wb[(r + 2) * RR + lane];
            a3 += __shfl_sync(0xffffffffu, st, r + 3) * wb[(r + 3) * RR + lane];
        }
        st = tanhf((a0 + a1) + (a2 + a3));
        g_cand[(size_t)(b * TT + t) * RR + lane] = st;
    }
}

// =================================================================
// K3: y = cand @ W_out[e] + x, LayerNorm -> g_hh (fp16 rna)
// =================================================================
__global__ void __launch_bounds__(256) k3_out_ln(
    const float* __restrict__ Wout,
    const float* __restrict__ gamma, const float* __restrict__ beta)
{
    const int n = blockIdx.x;
    const int tid = threadIdx.x;
    __shared__ float cs[RR];
    __shared__ float ssum[8], sqq[8];

    const int e = g_win[n];
    if (tid < RR) cs[tid] = g_cand[(size_t)n * RR + tid];
    __syncthreads();

    const float* wo = Wout + (size_t)e * RR * DM;
    float y[3];
#pragma unroll
    for (int j = 0; j < 3; j++) {
        const int d = tid + j * 256;
        float a = g_x[(size_t)n * DM + d];
#pragma unroll
        for (int r = 0; r < RR; r++) a += cs[r] * wo[r * DM + d];
        y[j] = a;
    }
    float s = y[0] + y[1] + y[2];
    float q = y[0]*y[0] + y[1]*y[1] + y[2]*y[2];
#pragma unroll
    for (int o = 16; o; o >>= 1) {
        s += __shfl_xor_sync(0xffffffffu, s, o);
        q += __shfl_xor_sync(0xffffffffu, q, o);
    }
    if ((tid & 31) == 0) { ssum[tid >> 5] = s; sqq[tid >> 5] = q; }
    __syncthreads();
    float st = 0.f, qt = 0.f;
#pragma unroll
    for (int i = 0; i < 8; i++) { st += ssum[i]; qt += sqq[i]; }
    const float mean = st * (1.0f / DM);
    const float var  = qt * (1.0f / DM) - mean * mean;
    const float inv  = rsqrtf(var + 1e-5f);
#pragma unroll
    for (int j = 0; j < 3; j++) {
        const int d = tid + j * 256;
        float v = (y[j] - mean) * inv * gamma[d] + beta[d];
        g_hh[(size_t)n * DM + d] = __float2half_rn(v);
    }
}

// =================================================================
// K4: logits = h @ Wemb^T, fp16 mma.sync m16n8k16, 128x128x32 tiles,
//     3-stage cp.async ring, XOR-swizzled smem + ldmatrix.
// =================================================================
#define BM4 128
#define BN4 128
#define BK4 32
#define TILEB (BM4*BK4*2)     // 8192 B per operand tile (fp16)
#define STAGEB (2*TILEB)      // 16384
#define NSTG 3
#define NIT (DM/BK4)          // 24
#define NBN ((VOCAB + BN4 - 1)/BN4)  // 393

// swizzled byte offset for (row, 16B-chunk kc in 0..3); rows are 64B, two per 128B line
__device__ __forceinline__ int swzf(int row, int kc) {
    int line = row >> 1;
    int cidx = ((row & 1) << 2) | kc;
    return line * 128 + ((cidx ^ (line & 7)) << 4);
}

__device__ __forceinline__ void cp16(void* dst, const void* src) {
    unsigned d = (unsigned)__cvta_generic_to_shared(dst);
    asm volatile("cp.async.cg.shared.global [%0], [%1], 16;\n" :: "r"(d), "l"(src));
}
__device__ __forceinline__ void cp16p(void* dst, const void* src, bool valid) {
    unsigned d = (unsigned)__cvta_generic_to_shared(dst);
    int sz = valid ? 16 : 0;
    asm volatile("cp.async.cg.shared.global [%0], [%1], 16, %2;\n" :: "r"(d), "l"(src), "r"(sz));
}
__device__ __forceinline__ void ldsm4(uint32_t r[4], uint32_t addr) {
    asm volatile("ldmatrix.sync.aligned.m8n8.x4.shared.b16 {%0,%1,%2,%3}, [%4];"
                 : "=r"(r[0]), "=r"(r[1]), "=r"(r[2]), "=r"(r[3]) : "r"(addr));
}
__device__ __forceinline__ void mma16(float c[4], const uint32_t a[4], const uint32_t b[2]) {
    asm volatile(
        "mma.sync.aligned.m16n8k16.row.col.f32.f16.f16.f32 "
        "{%0,%1,%2,%3}, {%4,%5,%6,%7}, {%8,%9}, {%0,%1,%2,%3};"
        : "+f"(c[0]), "+f"(c[1]), "+f"(c[2]), "+f"(c[3])
        : "r"(a[0]), "r"(a[1]), "r"(a[2]), "r"(a[3]), "r"(b[0]), "r"(b[1]));
}

__global__ void __launch_bounds__(256) k4_head(float* __restrict__ out)
{
    __shared__ alignas(128) char smc[NSTG * STAGEB];
    const unsigned sb = (unsigned)__cvta_generic_to_shared(smc);

    const int tid  = threadIdx.x;
    const int m0   = blockIdx.x * BM4;   // x = M: blocks sharing a B tile run adjacently
    const int n0   = blockIdx.y * BN4;
    const int warp = tid >> 5, lane = tid & 31;
    const int wm = warp >> 1, wn = warp & 1;     // 4 x 2 warp grid; warp tile 32x64
    const int grp = lane >> 2, tig = lane & 3;

    float c[2][8][4];
#pragma unroll
    for (int i = 0; i < 2; i++)
#pragma unroll
        for (int j = 0; j < 8; j++)
#pragma unroll
            for (int v = 0; v < 4; v++) c[i][j][v] = 0.f;

    // per-lane ldmatrix smem offsets (stage-relative)
    int aoff[2][2], boff[4][2];
    {
        const int tile = lane >> 3, rl = lane & 7;
#pragma unroll
        for (int mf = 0; mf < 2; mf++)
#pragma unroll
            for (int k16 = 0; k16 < 2; k16++) {
                int row = wm * 32 + mf * 16 + ((tile & 1) << 3) + rl;
                int kc  = k16 * 2 + (tile >> 1);
                aoff[mf][k16] = swzf(row, kc);
            }
#pragma unroll
        for (int np = 0; np < 4; np++)
#pragma unroll
            for (int k16 = 0; k16 < 2; k16++) {
                int row = wn * 64 + np * 16 + ((tile >> 1) << 3) + rl;
                int kc  = k16 * 2 + (tile & 1);
                boff[np][k16] = TILEB + swzf(row, kc);
            }
    }

    // loader: 512 16B-chunks per operand, 2 per thread
    auto load_stage = [&](int s, int k0) {
        char* base = smc + s * STAGEB;
#pragma unroll
        for (int p = 0; p < 2; p++) {
            const int q   = tid + p * 256;
            const int row = q >> 2, kc = q & 3;
            const int sw  = swzf(row, kc);
            cp16(base + sw, g_hh + (size_t)(m0 + row) * DM + k0 + kc * 8);
            const int nr = n0 + row;
            const bool v = nr < VOCAB;
            cp16p(base + TILEB + sw, g_wh + (size_t)(v ? nr : 0) * DM + k0 + kc * 8, v);
        }
    };

    load_stage(0, 0);
    asm volatile("cp.async.commit_group;" ::: "memory");
    load_stage(1, BK4);
    asm volatile("cp.async.commit_group;" ::: "memory");

    for (int it = 0; it < NIT; it++) {
        const int s = it % NSTG;
        if (it + 2 < NIT) {
            load_stage((it + 2) % NSTG, (it + 2) * BK4);
            asm volatile("cp.async.commit_group;" ::: "memory");
            asm volatile("cp.async.wait_group 2;" ::: "memory");
        } else {
            asm volatile("cp.async.wait_group 0;" ::: "memory");
        }
        __syncthreads();

        const unsigned Ab = sb + s * STAGEB;
#pragma unroll
        for (int k16 = 0; k16 < 2; k16++) {
            uint32_t a[2][4];
#pragma unroll
            for (int mf = 0; mf < 2; mf++) ldsm4(a[mf], Ab + aoff[mf][k16]);
            uint32_t b[8][2];
#pragma unroll
            for (int np = 0; np < 4; np++) {
                uint32_t r[4];
                ldsm4(r, Ab + boff[np][k16]);
                b[2*np][0]   = r[0]; b[2*np][1]   = r[1];
                b[2*np+1][0] = r[2]; b[2*np+1][1] = r[3];
            }
#pragma unroll
            for (int mf = 0; mf < 2; mf++)
#pragma unroll
                for (int nf = 0; nf < 8; nf++)
                    mma16(c[mf][nf], a[mf], b[nf]);
        }
        __syncthreads();   // compute done before this stage is overwritten
    }

    // epilogue: direct register stores (VOCAB odd -> scalar guarded)
#pragma unroll
    for (int mf = 0; mf < 2; mf++) {
        const int row = m0 + wm * 32 + mf * 16 + grp;
#pragma unroll
        for (int nf = 0; nf < 8; nf++) {
            const int col = n0 + wn * 64 + nf * 8 + (tig << 1);
            float* p0 = out + (size_t)row * VOCAB + col;
            float* p1 = p0 + (size_t)8 * VOCAB;
            if (col < VOCAB)     { p0[0] = c[mf][nf][0]; p1[0] = c[mf][nf][2]; }
            if (col + 1 < VOCAB) { p0[1] = c[mf][nf][1]; p1[1] = c[mf][nf][3]; }
        }
    }
}

// =================================================================
extern "C" void kernel_launch(void* const* d_in, const int* in_sizes, int n_in,
                              void* d_out, int out_size)
{
    const int*   idx   = (const int*)  d_in[0];
    const float* Wemb  = (const float*)d_in[1];
    const float* G     = (const float*)d_in[2];
    const float* Win   = (const float*)d_in[3];
    const float* Wrec  = (const float*)d_in[4];
    const float* Wout  = (const float*)d_in[5];
    const float* gamma = (const float*)d_in[6];
    const float* beta  = (const float*)d_in[7];
    float* out = (float*)d_out;

    k0_convert<<<(VOCAB * DM / 4 + 255) / 256, 256>>>((const float4*)Wemb);
    k1_embed_route<<<NTOK / 32, 256>>>(idx, Wemb, G, Win);
    k2_scan<<<BB, 128>>>(Wrec);
    k3_out_ln<<<NTOK, 256>>>(Wout, gamma, beta);

    dim3 g4(NTOK / BM4, NBN);
    k4_head<<<g4, 256>>>(out);
}

// round 12
// speedup vs baseline: 2.1455x; 1.7473x over previous
#include <cuda_runtime.h>
#include <cuda_fp16.h>
#include <cstdint>

#define VOCAB 50257
#define DM 768
#define NE 4
#define RR 32
#define BB 4
#define TT 512
#define NTOK (BB*TT)   // 2048

// ---------------- scratch (static device arrays; no allocation) ----------------
__device__ float  g_x[NTOK*DM];        // gathered embeddings [n][d] fp32
__device__ float  g_pre[NTOK*NE*RR];   // x @ W_in, [n][e*32+r]
__device__ int    g_win[NTOK];         // argmax expert per token
__device__ float  g_cand[NTOK*RR];     // winner's cand per token
__device__ __half g_hh[NTOK*DM];       // post-LN activations, fp16 (rna)
__device__ __half g_wh[VOCAB*DM];      // Wemb in fp16 (rna)

// =================================================================
// K0: Wemb fp32 -> fp16 (round-to-nearest)
// =================================================================
__global__ void __launch_bounds__(256) k0_convert(const float4* __restrict__ src)
{
    const int i = blockIdx.x * 256 + threadIdx.x;
    if (i < VOCAB * DM / 4) {
        float4 v = src[i];
        __half2 h0 = __floats2half2_rn(v.x, v.y);
        __half2 h1 = __floats2half2_rn(v.z, v.w);
        uint2 o;
        o.x = *(unsigned*)&h0;
        o.y = *(unsigned*)&h1;
        *(uint2*)&g_wh[(size_t)i * 4] = o;
    }
}

// =================================================================
// K1: embedding gather + pre = x@W_in (all experts) + routing argmax
// =================================================================
__global__ void __launch_bounds__(256) k1_embed_route(
    const int* __restrict__ idx, const float* __restrict__ Wemb,
    const float* __restrict__ G, const float* __restrict__ Win)
{
    __shared__ float xs[32][36];
    __shared__ float Ws[32][132];
    __shared__ float Gs[NE][32];
    __shared__ float sc[32][NE];

    const int tid = threadIdx.x;
    const int n0  = blockIdx.x * 32;

    float acc[4][4];
#pragma unroll
    for (int i = 0; i < 4; i++)
#pragma unroll
        for (int j = 0; j < 4; j++) acc[i][j] = 0.f;
    float accs = 0.f;

    const int tm = (tid >> 5) << 2;
    const int tn = (tid & 31) << 2;

    const int lrow = tid >> 3;
    const int lk   = (tid & 7) << 2;
    const float* xsrc = Wemb + (size_t)idx[n0 + lrow] * DM + lk;
    float*       xdst = g_x  + (size_t)(n0 + lrow) * DM + lk;

    const int i0 = tid * 16;
    const int wk = i0 >> 7;
    const int wc = i0 & 127;
    const int we = wc >> 5;
    const int wr = wc & 31;

    for (int kc = 0; kc < DM; kc += 32) {
        float4 xv = *(const float4*)(xsrc + kc);
        *(float4*)&xs[lrow][lk] = xv;
        *(float4*)(xdst + kc)   = xv;
        const float* wsrc = Win + (size_t)we * DM * RR + (size_t)(kc + wk) * RR + wr;
#pragma unroll
        for (int j = 0; j < 4; j++)
            *(float4*)&Ws[wk][wc + 4*j] = *(const float4*)(wsrc + 4*j);
        if (tid >= 128) {
            int j = tid - 128; int e = j >> 5; int r = j & 31;
            Gs[e][r] = G[e * DM + kc + r];
        }
        __syncthreads();

#pragma unroll
        for (int k = 0; k < 32; k++) {
            float4 bv = *(float4*)&Ws[k][tn];
            float a0 = xs[tm+0][k], a1 = xs[tm+1][k], a2 = xs[tm+2][k], a3 = xs[tm+3][k];
            acc[0][0] += a0*bv.x; acc[0][1] += a0*bv.y; acc[0][2] += a0*bv.z; acc[0][3] += a0*bv.w;
            acc[1][0] += a1*bv.x; acc[1][1] += a1*bv.y; acc[1][2] += a1*bv.z; acc[1][3] += a1*bv.w;
            acc[2][0] += a2*bv.x; acc[2][1] += a2*bv.y; acc[2][2] += a2*bv.z; acc[2][3] += a2*bv.w;
            acc[3][0] += a3*bv.x; acc[3][1] += a3*bv.y; acc[3][2] += a3*bv.z; acc[3][3] += a3*bv.w;
        }
        if (tid < 128) {
            int tok = tid >> 2, e = tid & 3;
#pragma unroll
            for (int k = 0; k < 32; k++) accs += xs[tok][k] * Gs[e][k];
        }
        __syncthreads();
    }

#pragma unroll
    for (int i = 0; i < 4; i++) {
        float4 v = make_float4(acc[i][0], acc[i][1], acc[i][2], acc[i][3]);
        *(float4*)&g_pre[(size_t)(n0 + tm + i) * (NE*RR) + tn] = v;
    }
    if (tid < 128) sc[tid >> 2][tid & 3] = accs;
    __syncthreads();
    if (tid < 32) {
        float best = sc[tid][0]; int be = 0;
#pragma unroll
        for (int e = 1; e < 4; e++) { float v = sc[tid][e]; if (v > best) { best = v; be = e; } }
        g_win[n0 + tid] = be;
    }
}

// =================================================================
// K2: per-expert chains are independent -> 1 warp per (batch, expert).
// =================================================================
__global__ void __launch_bounds__(128) k2_scan(const float* __restrict__ Wrec)
{
    __shared__ float ws[NE * RR * RR];
    __shared__ int   win_s[TT];
    __shared__ short lst[NE][TT];

    const int b = blockIdx.x, tid = threadIdx.x;
    const int w = tid >> 5, lane = tid & 31;

    for (int i = tid * 4; i < NE*RR*RR; i += 512)
        *(float4*)&ws[i] = *(const float4*)&Wrec[i];
    for (int i = tid; i < TT; i += 128)
        win_s[i] = g_win[b * TT + i];
    __syncthreads();

    int cnt = 0;
    for (int t0 = 0; t0 < TT; t0 += 32) {
        bool m = (win_s[t0 + lane] == w);
        unsigned bal = __ballot_sync(0xffffffffu, m);
        if (m) lst[w][cnt + __popc(bal & ((1u << lane) - 1u))] = (short)(t0 + lane);
        cnt += __popc(bal);
    }
    __syncwarp();

    const float* wb   = ws + w * (RR*RR);
    const float* preb = g_pre + (size_t)b * TT * (NE*RR) + w * RR + lane;

    float st = 0.f;
    float nxt = cnt ? preb[(int)lst[w][0] * (NE*RR)] : 0.f;
    for (int k = 0; k < cnt; k++) {
        const int t = lst[w][k];
        float pv = nxt;
        nxt = (k + 1 < cnt) ? preb[(int)lst[w][k + 1] * (NE*RR)] : 0.f;
        float a0 = pv, a1 = 0.f, a2 = 0.f, a3 = 0.f;
#pragma unroll
        for (int r = 0; r < RR; r += 4) {
            a0 += __shfl_sync(0xffffffffu, st, r)     * wb[(r    ) * RR + lane];
            a1 += __shfl_sync(0xffffffffu, st, r + 1) * wb[(r + 1) * RR + lane];
            a2 += __shfl_sync(0xffffffffu, st, r + 2) * wb[(r + 2) * RR + lane];
            a3 += __shfl_sync(0xffffffffu, st, r + 3) * wb[(r + 3) * RR + lane];
        }
        st = tanhf((a0 + a1) + (a2 + a3));
        g_cand[(size_t)(b * TT + t) * RR + lane] = st;
    }
}

// =================================================================
// K3: y = cand @ W_out[e] + x, LayerNorm -> g_hh (fp16 rna)
// =================================================================
__global__ void __launch_bounds__(256) k3_out_ln(
    const float* __restrict__ Wout,
    const float* __restrict__ gamma, const float* __restrict__ beta)
{
    const int n = blockIdx.x;
    const int tid = threadIdx.x;
    __shared__ float cs[RR];
    __shared__ float ssum[8], sqq[8];

    const int e = g_win[n];
    if (tid < RR) cs[tid] = g_cand[(size_t)n * RR + tid];
    __syncthreads();

    const float* wo = Wout + (size_t)e * RR * DM;
    float y[3];
#pragma unroll
    for (int j = 0; j < 3; j++) {
        const int d = tid + j * 256;
        float a = g_x[(size_t)n * DM + d];
#pragma unroll
        for (int r = 0; r < RR; r++) a += cs[r] * wo[r * DM + d];
        y[j] = a;
    }
    float s = y[0] + y[1] + y[2];
    float q = y[0]*y[0] + y[1]*y[1] + y[2]*y[2];
#pragma unroll
    for (int o = 16; o; o >>= 1) {
        s += __shfl_xor_sync(0xffffffffu, s, o);
        q += __shfl_xor_sync(0xffffffffu, q, o);
    }
    if ((tid & 31) == 0) { ssum[tid >> 5] = s; sqq[tid >> 5] = q; }
    __syncthreads();
    float st = 0.f, qt = 0.f;
#pragma unroll
    for (int i = 0; i < 8; i++) { st += ssum[i]; qt += sqq[i]; }
    const float mean = st * (1.0f / DM);
    const float var  = qt * (1.0f / DM) - mean * mean;
    const float inv  = rsqrtf(var + 1e-5f);
#pragma unroll
    for (int j = 0; j < 3; j++) {
        const int d = tid + j * 256;
        float v = (y[j] - mean) * inv * gamma[d] + beta[d];
        g_hh[(size_t)n * DM + d] = __float2half_rn(v);
    }
}

// =================================================================
// K4: logits = h @ Wemb^T, fp16 mma.sync m16n8k16, 128x128x64 tiles,
//     3-stage cp.async ring, ONE __syncthreads per iter, SW128 smem.
// =================================================================
#define BM4 128
#define BN4 128
#define BK4 64
#define TILEB (BM4*BK4*2)     // 16384 B per operand tile (fp16)
#define STAGEB (2*TILEB)      // 32768
#define NSTG 3
#define SMEM4 (NSTG*STAGEB)   // 98304
#define NIT (DM/BK4)          // 12
#define NBN ((VOCAB + BN4 - 1)/BN4)  // 393

// rows are 128B (64 halves); standard SW128 swizzle: kc in 0..7 (16B chunks)
__device__ __forceinline__ int swz8(int row, int kc) {
    return row * 128 + (((kc) ^ (row & 7)) << 4);
}

__device__ __forceinline__ void cp16(void* dst, const void* src) {
    unsigned d = (unsigned)__cvta_generic_to_shared(dst);
    asm volatile("cp.async.cg.shared.global [%0], [%1], 16;\n" :: "r"(d), "l"(src));
}
__device__ __forceinline__ void cp16p(void* dst, const void* src, bool valid) {
    unsigned d = (unsigned)__cvta_generic_to_shared(dst);
    int sz = valid ? 16 : 0;
    asm volatile("cp.async.cg.shared.global [%0], [%1], 16, %2;\n" :: "r"(d), "l"(src), "r"(sz));
}
__device__ __forceinline__ void ldsm4(uint32_t r[4], uint32_t addr) {
    asm volatile("ldmatrix.sync.aligned.m8n8.x4.shared.b16 {%0,%1,%2,%3}, [%4];"
                 : "=r"(r[0]), "=r"(r[1]), "=r"(r[2]), "=r"(r[3]) : "r"(addr));
}
__device__ __forceinline__ void mma16(float c[4], const uint32_t a[4], const uint32_t b[2]) {
    asm volatile(
        "mma.sync.aligned.m16n8k16.row.col.f32.f16.f16.f32 "
        "{%0,%1,%2,%3}, {%4,%5,%6,%7}, {%8,%9}, {%0,%1,%2,%3};"
        : "+f"(c[0]), "+f"(c[1]), "+f"(c[2]), "+f"(c[3])
        : "r"(a[0]), "r"(a[1]), "r"(a[2]), "r"(a[3]), "r"(b[0]), "r"(b[1]));
}
__device__ __forceinline__ void stcs(float* p, float v) {
    asm volatile("st.global.cs.f32 [%0], %1;" :: "l"(p), "f"(v));
}

__global__ void __launch_bounds__(256, 2) k4_head(float* __restrict__ out)
{
    extern __shared__ char smc[];
    const unsigned sb = (unsigned)__cvta_generic_to_shared(smc);

    const int tid  = threadIdx.x;
    const int m0   = blockIdx.x * BM4;   // x = M: blocks sharing a B tile run adjacently
    const int n0   = blockIdx.y * BN4;
    const int warp = tid >> 5, lane = tid & 31;
    const int wm = warp >> 1, wn = warp & 1;     // 4 x 2 warp grid; warp tile 32x64
    const int grp = lane >> 2, tig = lane & 3;

    float c[2][8][4];
#pragma unroll
    for (int i = 0; i < 2; i++)
#pragma unroll
        for (int j = 0; j < 8; j++)
#pragma unroll
            for (int v = 0; v < 4; v++) c[i][j][v] = 0.f;

    // per-lane ldmatrix row bases (row*128) + swizzle key (row&7) + kc bit
    const int tile = lane >> 3, rl = lane & 7;
    int aRow[2], aS[2];
    const int aKb = tile >> 1;           // kc low bit for A
#pragma unroll
    for (int mf = 0; mf < 2; mf++) {
        int row = wm * 32 + mf * 16 + ((tile & 1) << 3) + rl;
        aRow[mf] = row * 128; aS[mf] = row & 7;
    }
    int bRow[4], bS[4];
    const int bKb = tile & 1;            // kc low bit for B
#pragma unroll
    for (int np = 0; np < 4; np++) {
        int row = wn * 64 + np * 16 + ((tile >> 1) << 3) + rl;
        bRow[np] = TILEB + row * 128; bS[np] = row & 7;
    }

    // loader: 1024 16B-chunks per operand, 4 per thread per operand
    auto load_stage = [&](int s, int k0) {
        char* base = smc + s * STAGEB;
#pragma unroll
        for (int p = 0; p < 4; p++) {
            const int q   = tid + p * 256;
            const int row = q >> 3, kc = q & 7;
            const int sw  = swz8(row, kc);
            cp16(base + sw, g_hh + (size_t)(m0 + row) * DM + k0 + kc * 8);
            const int nr = n0 + row;
            const bool v = nr < VOCAB;
            cp16p(base + TILEB + sw, g_wh + (size_t)(v ? nr : 0) * DM + k0 + kc * 8, v);
        }
    };

    load_stage(0, 0);
    asm volatile("cp.async.commit_group;" ::: "memory");
    load_stage(1, BK4);
    asm volatile("cp.async.commit_group;" ::: "memory");

    for (int it = 0; it < NIT; it++) {
        const int s = it % NSTG;
        if (it + 1 < NIT) {
            asm volatile("cp.async.wait_group 1;" ::: "memory");   // group `it` done
        } else {
            asm volatile("cp.async.wait_group 0;" ::: "memory");
        }
        __syncthreads();   // stage `it` visible; all warps done computing it-1

        if (it + 2 < NIT) {   // slot (it+2)%3 == (it-1)%3, safe after the sync
            load_stage((it + 2) % NSTG, (it + 2) * BK4);
            asm volatile("cp.async.commit_group;" ::: "memory");
        }

        const unsigned Ab = sb + s * STAGEB;
#pragma unroll
        for (int k16 = 0; k16 < 4; k16++) {
            const int kc2 = k16 * 2;
            uint32_t a[2][4];
#pragma unroll
            for (int mf = 0; mf < 2; mf++)
                ldsm4(a[mf], Ab + aRow[mf] + (((kc2 + aKb) ^ aS[mf]) << 4));
            uint32_t b[8][2];
#pragma unroll
            for (int np = 0; np < 4; np++) {
                uint32_t r[4];
                ldsm4(r, Ab + bRow[np] + (((kc2 + bKb) ^ bS[np]) << 4));
                b[2*np][0]   = r[0]; b[2*np][1]   = r[1];
                b[2*np+1][0] = r[2]; b[2*np+1][1] = r[3];
            }
#pragma unroll
            for (int mf = 0; mf < 2; mf++)
#pragma unroll
                for (int nf = 0; nf < 8; nf++)
                    mma16(c[mf][nf], a[mf], b[nf]);
        }
    }

    // epilogue: streaming stores (output is write-once; keep Wemb in L2)
#pragma unroll
    for (int mf = 0; mf < 2; mf++) {
        const int row = m0 + wm * 32 + mf * 16 + grp;
#pragma unroll
        for (int nf = 0; nf < 8; nf++) {
            const int col = n0 + wn * 64 + nf * 8 + (tig << 1);
            float* p0 = out + (size_t)row * VOCAB + col;
            float* p1 = p0 + (size_t)8 * VOCAB;
            if (col < VOCAB)     { stcs(p0,     c[mf][nf][0]); stcs(p1,     c[mf][nf][2]); }
            if (col + 1 < VOCAB) { stcs(p0 + 1, c[mf][nf][1]); stcs(p1 + 1, c[mf][nf][3]); }
        }
    }
}

// =================================================================
extern "C" void kernel_launch(void* const* d_in, const int* in_sizes, int n_in,
                              void* d_out, int out_size)
{
    const int*   idx   = (const int*)  d_in[0];
    const float* Wemb  = (const float*)d_in[1];
    const float* G     = (const float*)d_in[2];
    const float* Win   = (const float*)d_in[3];
    const float* Wrec  = (const float*)d_in[4];
    const float* Wout  = (const float*)d_in[5];
    const float* gamma = (const float*)d_in[6];
    const float* beta  = (const float*)d_in[7];
    float* out = (float*)d_out;

    k0_convert<<<(VOCAB * DM / 4 + 255) / 256, 256>>>((const float4*)Wemb);
    k1_embed_route<<<NTOK / 32, 256>>>(idx, Wemb, G, Win);
    k2_scan<<<BB, 128>>>(Wrec);
    k3_out_ln<<<NTOK, 256>>>(Wout, gamma, beta);

    cudaFuncSetAttribute(k4_head, cudaFuncAttributeMaxDynamicSharedMemorySize, SMEM4);
    dim3 g4(NTOK / BM4, NBN);
    k4_head<<<g4, 256, SMEM4>>>(out);
}

// round 14
// speedup vs baseline: 2.2905x; 1.0676x over previous
#include <cuda_runtime.h>
#include <cuda_fp16.h>
#include <cstdint>

#define VOCAB 50257
#define DM 768
#define NE 4
#define RR 32
#define BB 4
#define TT 512
#define NTOK (BB*TT)   // 2048
#define NCB 1184       // conversion blocks appended to k1

// ---------------- scratch (static device arrays; no allocation) ----------------
__device__ float  g_x[NTOK*DM];        // gathered embeddings [n][d] fp32
__device__ float  g_pre[NTOK*NE*RR];   // x @ W_in, [n][e*32+r]
__device__ int    g_win[NTOK];         // argmax expert per token
__device__ float  g_cand[NTOK*RR];     // winner's cand per token
__device__ __half g_hh[NTOK*DM];       // post-LN activations, fp16 (rna)
__device__ __half g_wh[VOCAB*DM];      // Wemb in fp16 (rna)

// =================================================================
// K1 (fused): blocks [0,64): embedding gather + pre = x@W_in + routing argmax
//             blocks [64, 64+NCB): Wemb fp32 -> fp16 conversion (grid-stride)
// =================================================================
__global__ void __launch_bounds__(256) k1_embed_route(
    const int* __restrict__ idx, const float* __restrict__ Wemb,
    const float* __restrict__ G, const float* __restrict__ Win)
{
    if (blockIdx.x >= NTOK / 32) {
        // ---- conversion path: overlaps with routing blocks ----
        const float4* src = (const float4*)Wemb;
        const int cb = blockIdx.x - NTOK / 32;
        const int total = VOCAB * DM / 4;
        for (int i = cb * 256 + threadIdx.x; i < total; i += NCB * 256) {
            float4 v = src[i];
            __half2 h0 = __floats2half2_rn(v.x, v.y);
            __half2 h1 = __floats2half2_rn(v.z, v.w);
            uint2 o;
            o.x = *(unsigned*)&h0;
            o.y = *(unsigned*)&h1;
            *(uint2*)&g_wh[(size_t)i * 4] = o;
        }
        return;
    }

    __shared__ float xs[32][36];
    __shared__ float Ws[32][132];
    __shared__ float Gs[NE][32];
    __shared__ float sc[32][NE];

    const int tid = threadIdx.x;
    const int n0  = blockIdx.x * 32;

    float acc[4][4];
#pragma unroll
    for (int i = 0; i < 4; i++)
#pragma unroll
        for (int j = 0; j < 4; j++) acc[i][j] = 0.f;
    float accs = 0.f;

    const int tm = (tid >> 5) << 2;
    const int tn = (tid & 31) << 2;

    const int lrow = tid >> 3;
    const int lk   = (tid & 7) << 2;
    const float* xsrc = Wemb + (size_t)idx[n0 + lrow] * DM + lk;
    float*       xdst = g_x  + (size_t)(n0 + lrow) * DM + lk;

    const int i0 = tid * 16;
    const int wk = i0 >> 7;
    const int wc = i0 & 127;
    const int we = wc >> 5;
    const int wr = wc & 31;

    for (int kc = 0; kc < DM; kc += 32) {
        float4 xv = *(const float4*)(xsrc + kc);
        *(float4*)&xs[lrow][lk] = xv;
        *(float4*)(xdst + kc)   = xv;
        const float* wsrc = Win + (size_t)we * DM * RR + (size_t)(kc + wk) * RR + wr;
#pragma unroll
        for (int j = 0; j < 4; j++)
            *(float4*)&Ws[wk][wc + 4*j] = *(const float4*)(wsrc + 4*j);
        if (tid >= 128) {
            int j = tid - 128; int e = j >> 5; int r = j & 31;
            Gs[e][r] = G[e * DM + kc + r];
        }
        __syncthreads();

#pragma unroll
        for (int k = 0; k < 32; k++) {
            float4 bv = *(float4*)&Ws[k][tn];
            float a0 = xs[tm+0][k], a1 = xs[tm+1][k], a2 = xs[tm+2][k], a3 = xs[tm+3][k];
            acc[0][0] += a0*bv.x; acc[0][1] += a0*bv.y; acc[0][2] += a0*bv.z; acc[0][3] += a0*bv.w;
            acc[1][0] += a1*bv.x; acc[1][1] += a1*bv.y; acc[1][2] += a1*bv.z; acc[1][3] += a1*bv.w;
            acc[2][0] += a2*bv.x; acc[2][1] += a2*bv.y; acc[2][2] += a2*bv.z; acc[2][3] += a2*bv.w;
            acc[3][0] += a3*bv.x; acc[3][1] += a3*bv.y; acc[3][2] += a3*bv.z; acc[3][3] += a3*bv.w;
        }
        if (tid < 128) {
            int tok = tid >> 2, e = tid & 3;
#pragma unroll
            for (int k = 0; k < 32; k++) accs += xs[tok][k] * Gs[e][k];
        }
        __syncthreads();
    }

#pragma unroll
    for (int i = 0; i < 4; i++) {
        float4 v = make_float4(acc[i][0], acc[i][1], acc[i][2], acc[i][3]);
        *(float4*)&g_pre[(size_t)(n0 + tm + i) * (NE*RR) + tn] = v;
    }
    if (tid < 128) sc[tid >> 2][tid & 3] = accs;
    __syncthreads();
    if (tid < 32) {
        float best = sc[tid][0]; int be = 0;
#pragma unroll
        for (int e = 1; e < 4; e++) { float v = sc[tid][e]; if (v > best) { best = v; be = e; } }
        g_win[n0 + tid] = be;
    }
}

// =================================================================
// K2: per-expert chains are independent -> 1 warp per (batch, expert).
// =================================================================
__global__ void __launch_bounds__(128) k2_scan(const float* __restrict__ Wrec)
{
    __shared__ float ws[NE * RR * RR];
    __shared__ int   win_s[TT];
    __shared__ short lst[NE][TT];

    const int b = blockIdx.x, tid = threadIdx.x;
    const int w = tid >> 5, lane = tid & 31;

    for (int i = tid * 4; i < NE*RR*RR; i += 512)
        *(float4*)&ws[i] = *(const float4*)&Wrec[i];
    for (int i = tid; i < TT; i += 128)
        win_s[i] = g_win[b * TT + i];
    __syncthreads();

    int cnt = 0;
    for (int t0 = 0; t0 < TT; t0 += 32) {
        bool m = (win_s[t0 + lane] == w);
        unsigned bal = __ballot_sync(0xffffffffu, m);
        if (m) lst[w][cnt + __popc(bal & ((1u << lane) - 1u))] = (short)(t0 + lane);
        cnt += __popc(bal);
    }
    __syncwarp();

    const float* wb   = ws + w * (RR*RR);
    const float* preb = g_pre + (size_t)b * TT * (NE*RR) + w * RR + lane;

    float st = 0.f;
    float nxt = cnt ? preb[(int)lst[w][0] * (NE*RR)] : 0.f;
    for (int k = 0; k < cnt; k++) {
        const int t = lst[w][k];
        float pv = nxt;
        nxt = (k + 1 < cnt) ? preb[(int)lst[w][k + 1] * (NE*RR)] : 0.f;
        float a0 = pv, a1 = 0.f, a2 = 0.f, a3 = 0.f;
#pragma unroll
        for (int r = 0; r < RR; r += 4) {
            a0 += __shfl_sync(0xffffffffu, st, r)     * wb[(r    ) * RR + lane];
            a1 += __shfl_sync(0xffffffffu, st, r + 1) * wb[(r + 1) * RR + lane];
            a2 += __shfl_sync(0xffffffffu, st, r + 2) * wb[(r + 2) * RR + lane];
            a3 += __shfl_sync(0xffffffffu, st, r + 3) * wb[(r + 3) * RR + lane];
        }
        st = tanhf((a0 + a1) + (a2 + a3));
        g_cand[(size_t)(b * TT + t) * RR + lane] = st;
    }
}

// =================================================================
// K3: y = cand @ W_out[e] + x, LayerNorm -> g_hh (fp16 rna)
// =================================================================
__global__ void __launch_bounds__(256) k3_out_ln(
    const float* __restrict__ Wout,
    const float* __restrict__ gamma, const float* __restrict__ beta)
{
    const int n = blockIdx.x;
    const int tid = threadIdx.x;
    __shared__ float cs[RR];
    __shared__ float ssum[8], sqq[8];

    const int e = g_win[n];
    if (tid < RR) cs[tid] = g_cand[(size_t)n * RR + tid];
    __syncthreads();

    const float* wo = Wout + (size_t)e * RR * DM;
    float y[3];
#pragma unroll
    for (int j = 0; j < 3; j++) {
        const int d = tid + j * 256;
        float a = g_x[(size_t)n * DM + d];
#pragma unroll
        for (int r = 0; r < RR; r++) a += cs[r] * wo[r * DM + d];
        y[j] = a;
    }
    float s = y[0] + y[1] + y[2];
    float q = y[0]*y[0] + y[1]*y[1] + y[2]*y[2];
#pragma unroll
    for (int o = 16; o; o >>= 1) {
        s += __shfl_xor_sync(0xffffffffu, s, o);
        q += __shfl_xor_sync(0xffffffffu, q, o);
    }
    if ((tid & 31) == 0) { ssum[tid >> 5] = s; sqq[tid >> 5] = q; }
    __syncthreads();
    float st = 0.f, qt = 0.f;
#pragma unroll
    for (int i = 0; i < 8; i++) { st += ssum[i]; qt += sqq[i]; }
    const float mean = st * (1.0f / DM);
    const float var  = qt * (1.0f / DM) - mean * mean;
    const float inv  = rsqrtf(var + 1e-5f);
#pragma unroll
    for (int j = 0; j < 3; j++) {
        const int d = tid + j * 256;
        float v = (y[j] - mean) * inv * gamma[d] + beta[d];
        g_hh[(size_t)n * DM + d] = __float2half_rn(v);
    }
}

// =================================================================
// K4: logits = h @ Wemb^T, fp16 mma.sync m16n8k16, 128x128x64 tiles,
//     3-stage cp.async ring, 1 sync/iter, double-buffered ldmatrix frags.
// =================================================================
#define BM4 128
#define BN4 128
#define BK4 64
#define TILEB (BM4*BK4*2)     // 16384 B per operand tile (fp16)
#define STAGEB (2*TILEB)      // 32768
#define NSTG 3
#define SMEM4 (NSTG*STAGEB)   // 98304
#define NIT (DM/BK4)          // 12
#define NBN ((VOCAB + BN4 - 1)/BN4)  // 393

// rows are 128B (64 halves); standard SW128 swizzle: kc in 0..7 (16B chunks)
__device__ __forceinline__ int swz8(int row, int kc) {
    return row * 128 + (((kc) ^ (row & 7)) << 4);
}

__device__ __forceinline__ void cp16(void* dst, const void* src) {
    unsigned d = (unsigned)__cvta_generic_to_shared(dst);
    asm volatile("cp.async.cg.shared.global [%0], [%1], 16;\n" :: "r"(d), "l"(src));
}
__device__ __forceinline__ void cp16p(void* dst, const void* src, bool valid) {
    unsigned d = (unsigned)__cvta_generic_to_shared(dst);
    int sz = valid ? 16 : 0;
    asm volatile("cp.async.cg.shared.global [%0], [%1], 16, %2;\n" :: "r"(d), "l"(src), "r"(sz));
}
__device__ __forceinline__ void ldsm4(uint32_t r[4], uint32_t addr) {
    asm volatile("ldmatrix.sync.aligned.m8n8.x4.shared.b16 {%0,%1,%2,%3}, [%4];"
                 : "=r"(r[0]), "=r"(r[1]), "=r"(r[2]), "=r"(r[3]) : "r"(addr));
}
__device__ __forceinline__ void mma16(float c[4], const uint32_t a[4], const uint32_t b[2]) {
    asm volatile(
        "mma.sync.aligned.m16n8k16.row.col.f32.f16.f16.f32 "
        "{%0,%1,%2,%3}, {%4,%5,%6,%7}, {%8,%9}, {%0,%1,%2,%3};"
        : "+f"(c[0]), "+f"(c[1]), "+f"(c[2]), "+f"(c[3])
        : "r"(a[0]), "r"(a[1]), "r"(a[2]), "r"(a[3]), "r"(b[0]), "r"(b[1]));
}
__device__ __forceinline__ void stcs(float* p, float v) {
    asm volatile("st.global.cs.f32 [%0], %1;" :: "l"(p), "f"(v));
}

__global__ void __launch_bounds__(256, 2) k4_head(float* __restrict__ out)
{
    extern __shared__ char smc[];
    const unsigned sb = (unsigned)__cvta_generic_to_shared(smc);

    const int tid  = threadIdx.x;
    const int m0   = blockIdx.x * BM4;   // x = M: blocks sharing a B tile run adjacently
    const int n0   = blockIdx.y * BN4;
    const int warp = tid >> 5, lane = tid & 31;
    const int wm = warp >> 1, wn = warp & 1;     // 4 x 2 warp grid; warp tile 32x64
    const int grp = lane >> 2, tig = lane & 3;

    float c[2][8][4];
#pragma unroll
    for (int i = 0; i < 2; i++)
#pragma unroll
        for (int j = 0; j < 8; j++)
#pragma unroll
            for (int v = 0; v < 4; v++) c[i][j][v] = 0.f;

    // per-lane ldmatrix row bases (row*128) + swizzle key (row&7) + kc bit
    const int tile = lane >> 3, rl = lane & 7;
    int aRow[2], aS[2];
    const int aKb = tile >> 1;           // kc low bit for A
#pragma unroll
    for (int mf = 0; mf < 2; mf++) {
        int row = wm * 32 + mf * 16 + ((tile & 1) << 3) + rl;
        aRow[mf] = row * 128; aS[mf] = row & 7;
    }
    int bRow[4], bS[4];
    const int bKb = tile & 1;            // kc low bit for B
#pragma unroll
    for (int np = 0; np < 4; np++) {
        int row = wn * 64 + np * 16 + ((tile >> 1) << 3) + rl;
        bRow[np] = TILEB + row * 128; bS[np] = row & 7;
    }

    // loader: 1024 16B-chunks per operand, 4 per thread per operand
    auto load_stage = [&](int s, int k0) {
        char* base = smc + s * STAGEB;
#pragma unroll
        for (int p = 0; p < 4; p++) {
            const int q   = tid + p * 256;
            const int row = q >> 3, kc = q & 7;
            const int sw  = swz8(row, kc);
            cp16(base + sw, g_hh + (size_t)(m0 + row) * DM + k0 + kc * 8);
            const int nr = n0 + row;
            const bool v = nr < VOCAB;
            cp16p(base + TILEB + sw, g_wh + (size_t)(v ? nr : 0) * DM + k0 + kc * 8, v);
        }
    };

    auto ld_frags = [&](unsigned Ab, int k16, uint32_t a[2][4], uint32_t b[8][2]) {
        const int kc2 = k16 * 2;
#pragma unroll
        for (int mf = 0; mf < 2; mf++)
            ldsm4(a[mf], Ab + aRow[mf] + (((kc2 + aKb) ^ aS[mf]) << 4));
#pragma unroll
        for (int np = 0; np < 4; np++) {
            uint32_t r[4];
            ldsm4(r, Ab + bRow[np] + (((kc2 + bKb) ^ bS[np]) << 4));
            b[2*np][0]   = r[0]; b[2*np][1]   = r[1];
            b[2*np+1][0] = r[2]; b[2*np+1][1] = r[3];
        }
    };

    load_stage(0, 0);
    asm volatile("cp.async.commit_group;" ::: "memory");
    load_stage(1, BK4);
    asm volatile("cp.async.commit_group;" ::: "memory");

    uint32_t af[2][2][4], bf[2][8][2];

    for (int it = 0; it < NIT; it++) {
        const int s = it % NSTG;
        if (it + 1 < NIT) {
            asm volatile("cp.async.wait_group 1;" ::: "memory");   // group `it` done
        } else {
            asm volatile("cp.async.wait_group 0;" ::: "memory");
        }
        __syncthreads();   // stage `it` visible; all warps done computing it-1

        if (it + 2 < NIT) {   // slot (it+2)%3 == (it-1)%3, safe after the sync
            load_stage((it + 2) % NSTG, (it + 2) * BK4);
            asm volatile("cp.async.commit_group;" ::: "memory");
        }

        const unsigned Ab = sb + s * STAGEB;
        ld_frags(Ab, 0, af[0], bf[0]);     // prime k16=0
#pragma unroll
        for (int k16 = 0; k16 < 4; k16++) {
            const int cur = k16 & 1;
            if (k16 < 3)                    // prefetch next chunk's frags
                ld_frags(Ab, k16 + 1, af[cur ^ 1], bf[cur ^ 1]);
#pragma unroll
            for (int mf = 0; mf < 2; mf++)
#pragma unroll
                for (int nf = 0; nf < 8; nf++)
                    mma16(c[mf][nf], af[cur][mf], bf[cur][nf]);
        }
    }

    // epilogue: streaming stores (output is write-once; keep Wemb in L2)
#pragma unroll
    for (int mf = 0; mf < 2; mf++) {
        const int row = m0 + wm * 32 + mf * 16 + grp;
#pragma unroll
        for (int nf = 0; nf < 8; nf++) {
            const int col = n0 + wn * 64 + nf * 8 + (tig << 1);
            float* p0 = out + (size_t)row * VOCAB + col;
            float* p1 = p0 + (size_t)8 * VOCAB;
            if (col < VOCAB)     { stcs(p0,     c[mf][nf][0]); stcs(p1,     c[mf][nf][2]); }
            if (col + 1 < VOCAB) { stcs(p0 + 1, c[mf][nf][1]); stcs(p1 + 1, c[mf][nf][3]); }
        }
    }
}

// =================================================================
extern "C" void kernel_launch(void* const* d_in, const int* in_sizes, int n_in,
                              void* d_out, int out_size)
{
    const int*   idx   = (const int*)  d_in[0];
    const float* Wemb  = (const float*)d_in[1];
    const float* G     = (const float*)d_in[2];
    const float* Win   = (const float*)d_in[3];
    const float* Wrec  = (const float*)d_in[4];
    const float* Wout  = (const float*)d_in[5];
    const float* gamma = (const float*)d_in[6];
    const float* beta  = (const float*)d_in[7];
    float* out = (float*)d_out;

    k1_embed_route<<<NTOK / 32 + NCB, 256>>>(idx, Wemb, G, Win);
    k2_scan<<<BB, 128>>>(Wrec);
    k3_out_ln<<<NTOK, 256>>>(Wout, gamma, beta);

    cudaFuncSetAttribute(k4_head, cudaFuncAttributeMaxDynamicSharedMemorySize, SMEM4);
    dim3 g4(NTOK / BM4, NBN);
    k4_head<<<g4, 256, SMEM4>>>(out);
}